// round 7
// baseline (speedup 1.0000x reference)
#include <cuda_runtime.h>
#include <cstdint>

// ---------------------------------------------------------------------------
// Problem constants
// ---------------------------------------------------------------------------
#define BB    32
#define TT    1024
#define CC    512
#define DD    256
#define UU    256
#define OO    256
#define MTOT  (BB*TT)          // 32768

__device__ float g_xin[(size_t)MTOT * DD];
__device__ float g_xz [(size_t)MTOT * 4 * UU];
__device__ float g_hs [(size_t)MTOT * UU];

// 1 noop: ncu capture lands on absolute launch idx 3 => the LSTM kernel
__global__ void noop_kernel(int* p) { if (p) *p = 0; }

// ---------------------------------------------------------------------------
// Tiled fp32 GEMM (unchanged): C[M,N] = A[M,K] @ W[K,N] + bias[N]
// ---------------------------------------------------------------------------
__global__ __launch_bounds__(256) void gemm_bias_kernel(
    const float* __restrict__ A, const float* __restrict__ W,
    const float* __restrict__ bias, float* __restrict__ C,
    int M, int N, int K)
{
    __shared__ float As[16][128];
    __shared__ float Bs[16][64];

    const int tid = threadIdx.x;
    const int tx  = tid & 15;
    const int ty  = tid >> 4;
    const int m0  = blockIdx.y * 128;
    const int n0  = blockIdx.x * 64;

    const int arow = tid >> 2;
    const int akc  = (tid & 3) * 4;
    const int brow = tid >> 4;
    const int bnc  = (tid & 15) * 4;

    float acc[8][4];
    #pragma unroll
    for (int i = 0; i < 8; i++)
        #pragma unroll
        for (int j = 0; j < 4; j++) acc[i][j] = 0.f;

    for (int kt = 0; kt < K; kt += 16) {
        #pragma unroll
        for (int h = 0; h < 2; h++) {
            int r = arow + h * 64;
            float4 a = *(const float4*)&A[(size_t)(m0 + r) * K + kt + akc];
            As[akc + 0][r] = a.x;
            As[akc + 1][r] = a.y;
            As[akc + 2][r] = a.z;
            As[akc + 3][r] = a.w;
        }
        {
            float4 b = *(const float4*)&W[(size_t)(kt + brow) * N + n0 + bnc];
            *(float4*)&Bs[brow][bnc] = b;
        }
        __syncthreads();

        #pragma unroll
        for (int kk = 0; kk < 16; kk++) {
            float4 b4 = *(const float4*)&Bs[kk][tx * 4];
            float4 a0 = *(const float4*)&As[kk][ty * 8];
            float4 a1 = *(const float4*)&As[kk][ty * 8 + 4];
            float a[8] = {a0.x, a0.y, a0.z, a0.w, a1.x, a1.y, a1.z, a1.w};
            #pragma unroll
            for (int i = 0; i < 8; i++) {
                acc[i][0] += a[i] * b4.x;
                acc[i][1] += a[i] * b4.y;
                acc[i][2] += a[i] * b4.z;
                acc[i][3] += a[i] * b4.w;
            }
        }
        __syncthreads();
    }

    float4 bv = *(const float4*)&bias[n0 + tx * 4];
    #pragma unroll
    for (int i = 0; i < 8; i++) {
        float4 o;
        o.x = acc[i][0] + bv.x;
        o.y = acc[i][1] + bv.y;
        o.z = acc[i][2] + bv.z;
        o.w = acc[i][3] + bv.w;
        *(float4*)&C[(size_t)(m0 + ty * 8 + i) * N + n0 + tx * 4] = o;
    }
}

// ---------------------------------------------------------------------------
// LSTM scan v6: 512 threads / 16 warps, k-pair packed R (zero-mov MMA loop).
//   warp w: k-chunk kc=w&7 (32 k), col-half ch=w>>3.
//   thread: cols c0=ch*64+2l, c1=c0+1; Rreg packed over k-pairs:
//     R0[j]={R[kc*32+2j,c0],R[kc*32+2j+1,c0]}, R1[j] same for c1 (16 u64 each).
//   h2 layout [buf][blk=8][b=2][u=32]: k-pair for batch b is a contiguous
//   LDS.64; rank r's push remains ONE contiguous 256B block.
//   Inner loop: 16 x (2 LDS.64 + 4 FMA2) -- no packing movs.
// ---------------------------------------------------------------------------
#define CLS 8
#define LSTM_THREADS 512

__device__ __forceinline__ float sigm_f(float x) {
    return 1.f / (1.f + __expf(-x));
}
__device__ __forceinline__ float tanh_f(float x) {
    return 2.f / (1.f + __expf(-2.f * x)) - 1.f;
}

#define FMA2(acc, a, b) \
    asm("fma.rn.f32x2 %0, %1, %2, %0;" : "+l"(acc) : "l"(a), "l"(b))

#define MBAR_INIT(addr, cnt) \
    asm volatile("mbarrier.init.shared.b64 [%0], %1;" :: "r"(addr), "r"(cnt) : "memory")

#define MBAR_EXPECT_TX(addr, tx) \
    asm volatile("mbarrier.arrive.expect_tx.shared.b64 _, [%0], %1;" :: "r"(addr), "r"(tx) : "memory")

#define MBAR_WAIT(addr, par) do {                                                  \
    asm volatile("{\n\t.reg .pred P;\n"                                            \
                 "W_%=:\n\t"                                                       \
                 "mbarrier.try_wait.parity.acquire.cluster.shared::cta.b64 "       \
                 "P, [%0], %1, 0x80;\n\t"                                          \
                 "@!P bra W_%=;\n\t}"                                              \
                 :: "r"(addr), "r"(par) : "memory");                               \
} while (0)

__global__ void __cluster_dims__(CLS, 1, 1) __launch_bounds__(LSTM_THREADS, 1)
lstm_kernel(const float* __restrict__ xz, const float* __restrict__ R,
            float* __restrict__ hs)
{
    __shared__ __align__(16) float h2[2 * 512];            // [buf][blk8][b2][u32]
    __shared__ __align__(16) float parts[2 * 8 * 2 * 128]; // [buf][kc][b][c]
    __shared__ __align__(16) float hstage[64];             // [b2][u32]
    __shared__ __align__(8)  unsigned long long mbar[16];  // [buf][src=8]

    const int tid  = threadIdx.x;
    const int rank = blockIdx.x;
    const int b0   = blockIdx.y * 2;
    const int w    = tid >> 5;
    const int l    = tid & 31;
    const int kc   = w & 7;              // k-chunk (= source rank we wait on)
    const int ch   = w >> 3;             // column half

    // ---- R sub-tile -> registers, packed over k-pairs
    const int c0 = ch * 64 + 2 * l;
    const int c1 = c0 + 1;
    const int gcol0 = (c0 >> 5) * 256 + rank * 32 + (c0 & 31);
    const int gcol1 = (c1 >> 5) * 256 + rank * 32 + (c1 & 31);
    unsigned long long R0[16], R1[16];
    #pragma unroll
    for (int j = 0; j < 16; j++) {
        const float* r0 = &R[(size_t)(kc * 32 + 2 * j) * 1024];
        const float* r1 = &R[(size_t)(kc * 32 + 2 * j + 1) * 1024];
        unsigned lo0 = __float_as_uint(r0[gcol0]);
        unsigned hi0 = __float_as_uint(r1[gcol0]);
        unsigned lo1 = __float_as_uint(r0[gcol1]);
        unsigned hi1 = __float_as_uint(r1[gcol1]);
        R0[j] = ((unsigned long long)hi0 << 32) | lo0;
        R1[j] = ((unsigned long long)hi1 << 32) | lo1;
    }

    for (int i = tid; i < 1024; i += LSTM_THREADS) h2[i] = 0.f;

    const unsigned mb0 = (unsigned)__cvta_generic_to_shared(&mbar[0]);
    if (tid == 0) {
        #pragma unroll
        for (int i = 0; i < 16; i++) {
            MBAR_INIT(mb0 + i * 8, 1);
            MBAR_EXPECT_TX(mb0 + i * 8, 256);
        }
        asm volatile("fence.mbarrier_init.release.cluster;" ::: "memory");
    }
    __syncthreads();
    asm volatile("barrier.cluster.arrive.aligned;" ::: "memory");
    asm volatile("barrier.cluster.wait.aligned;"   ::: "memory");

    const int gb = tid >> 5;             // gate-thread batch (tid<64)
    const int gu = tid & 31;             // gate-thread unit
    float creg = 0.f;
    int ph0 = 0, ph1 = 0;

    unsigned rdl = 0, rml = 0;           // remote push addrs (threads 0..7)
    if (tid < 8) {
        const unsigned dl0 = (unsigned)__cvta_generic_to_shared(&h2[rank * 64]);
        const unsigned ml0 = mb0 + (unsigned)(rank * 8);
        asm volatile("mapa.shared::cluster.u32 %0, %1, %2;"
                     : "=r"(rdl) : "r"(dl0), "r"(tid));
        asm volatile("mapa.shared::cluster.u32 %0, %1, %2;"
                     : "=r"(rml) : "r"(ml0), "r"(tid));
    }
    const unsigned src_l = (unsigned)__cvta_generic_to_shared(&hstage[0]);
    const unsigned mwait0 = mb0 + (unsigned)(kc * 8);

    for (int t = 0; t < TT; t++) {
        const int pb = t & 1;

        // xz prefetch (gate threads), before any wait
        float xzv0 = 0.f, xzv1 = 0.f, xzv2 = 0.f, xzv3 = 0.f;
        if (tid < 64) {
            size_t base = ((size_t)(b0 + gb) * TT + t) * 1024 + rank * 32 + gu;
            xzv0 = xz[base];
            xzv1 = xz[base + 256];
            xzv2 = xz[base + 512];
            xzv3 = xz[base + 768];
        }

        // wait only for slice kc (pushed by rank kc)
        if (t > 0) {
            const unsigned m = mwait0 + (unsigned)(pb * 64);
            if (pb) { MBAR_WAIT(m, ph1); ph1 ^= 1; }
            else    { MBAR_WAIT(m, ph0); ph0 ^= 1; }
            if (l == 0 && w < 8) MBAR_EXPECT_TX(m, 256);  // re-arm for t+2
        }

        // ---- MMA: cols c0,c1; k-pairs j=0..15 within block kc; batches 0,1
        unsigned long long a00 = 0ull, a01 = 0ull, a10 = 0ull, a11 = 0ull;
        const float* hblk = h2 + pb * 512 + kc * 64;   // [b2][u32]
        #pragma unroll
        for (int j = 0; j < 16; j++) {
            unsigned long long hp0 = *(const unsigned long long*)&hblk[2 * j];
            unsigned long long hp1 = *(const unsigned long long*)&hblk[32 + 2 * j];
            FMA2(a00, R0[j], hp0);   // c0, b0
            FMA2(a01, R0[j], hp1);   // c0, b1
            FMA2(a10, R1[j], hp0);   // c1, b0
            FMA2(a11, R1[j], hp1);   // c1, b1
        }
        {
            float* pbuf = parts + pb * 2048;
            unsigned x0, x1, y0, y1;
            asm("mov.b64 {%0, %1}, %2;" : "=r"(x0), "=r"(x1) : "l"(a00));
            asm("mov.b64 {%0, %1}, %2;" : "=r"(y0), "=r"(y1) : "l"(a10));
            *(float2*)&pbuf[(kc * 2 + 0) * 128 + c0] = make_float2(
                __uint_as_float(x0) + __uint_as_float(x1),
                __uint_as_float(y0) + __uint_as_float(y1));
            asm("mov.b64 {%0, %1}, %2;" : "=r"(x0), "=r"(x1) : "l"(a01));
            asm("mov.b64 {%0, %1}, %2;" : "=r"(y0), "=r"(y1) : "l"(a11));
            *(float2*)&pbuf[(kc * 2 + 1) * 128 + c0] = make_float2(
                __uint_as_float(x0) + __uint_as_float(x1),
                __uint_as_float(y0) + __uint_as_float(y1));
        }

        if (w >= 2) {
            asm volatile("bar.arrive 2, %0;" :: "n"(LSTM_THREADS) : "memory");
            continue;
        }
        asm volatile("bar.sync 2, %0;" :: "n"(LSTM_THREADS) : "memory");

        // ---- gate phase (warps 0,1 = 64 gate threads) ----
        {
            const float* pbuf = parts + pb * 2048;
            float z0 = xzv0, z1 = xzv1, z2 = xzv2, z3 = xzv3;
            #pragma unroll
            for (int kk = 0; kk < 8; kk++) {
                const float* p = &pbuf[(kk * 2 + gb) * 128];
                z0 += p[gu];
                z1 += p[32 + gu];
                z2 += p[64 + gu];
                z3 += p[96 + gu];
            }
            float ig = sigm_f(z0);
            float fg = sigm_f(z1);
            float gg = tanh_f(z2);
            float og = sigm_f(z3);
            creg = fg * creg + ig * gg;
            float h = og * tanh_f(creg);

            if (t < TT - 1) {
                hstage[gb * 32 + gu] = h;       // [b][u] matches dst block
                asm volatile("bar.sync 1, 64;" ::: "memory");
                if (tid < 8) {
                    asm volatile("fence.proxy.async.shared::cta;" ::: "memory");
                    const int nb = pb ^ 1;
                    const unsigned rd = rdl + (unsigned)(nb * 2048);
                    const unsigned rm = rml + (unsigned)(nb * 64);
                    asm volatile(
                        "cp.async.bulk.shared::cluster.shared::cta"
                        ".mbarrier::complete_tx::bytes [%0], [%1], 256, [%2];"
                        :: "r"(rd), "r"(src_l), "r"(rm) : "memory");
                }
            }
            hs[((size_t)(b0 + gb) * TT + t) * UU + rank * 32 + gu] = h;
        }
    }

    asm volatile("barrier.cluster.arrive.aligned;" ::: "memory");
    asm volatile("barrier.cluster.wait.aligned;"   ::: "memory");
}

// ---------------------------------------------------------------------------
// launch
// ---------------------------------------------------------------------------
extern "C" void kernel_launch(void* const* d_in, const int* in_sizes, int n_in,
                              void* d_out, int out_size)
{
    const float* x      = (const float*)d_in[0];
    const float* w_in   = (const float*)d_in[1];
    const float* b_in   = (const float*)d_in[2];
    const float* kernel = (const float*)d_in[3];
    const float* rec_k  = (const float*)d_in[4];
    const float* bias   = (const float*)d_in[5];
    const float* w_out  = (const float*)d_in[6];
    const float* b_out  = (const float*)d_in[7];
    float* out = (float*)d_out;

    float *p_xin, *p_xz, *p_hs;
    cudaGetSymbolAddress((void**)&p_xin, g_xin);
    cudaGetSymbolAddress((void**)&p_xz,  g_xz);
    cudaGetSymbolAddress((void**)&p_hs,  g_hs);

    // 1 noop: LSTM becomes absolute launch idx 3 == the ncu capture target
    noop_kernel<<<1, 32>>>(nullptr);

    // 1) xin = x @ w_in + b_in          [32768,512]x[512,256]
    gemm_bias_kernel<<<dim3(DD / 64, MTOT / 128), 256>>>(
        x, w_in, b_in, p_xin, MTOT, DD, CC);

    // 2) xz = xin @ kernel + bias       [32768,256]x[256,1024]
    gemm_bias_kernel<<<dim3((4 * UU) / 64, MTOT / 128), 256>>>(
        p_xin, kernel, bias, p_xz, MTOT, 4 * UU, DD);

    // 3) LSTM scan over T=1024
    lstm_kernel<<<dim3(CLS, BB / 2), LSTM_THREADS>>>(p_xz, rec_k, p_hs);

    // 4) out = hs @ w_out + b_out       [32768,256]x[256,256]
    gemm_bias_kernel<<<dim3(OO / 64, MTOT / 128), 256>>>(
        p_hs, w_out, b_out, out, MTOT, OO, UU);
}

// round 8
// speedup vs baseline: 1.5615x; 1.5615x over previous
#include <cuda_runtime.h>
#include <cstdint>

// ---------------------------------------------------------------------------
// Problem constants
// ---------------------------------------------------------------------------
#define BB    32
#define TT    1024
#define CC    512
#define DD    256
#define UU    256
#define OO    256
#define MTOT  (BB*TT)          // 32768

__device__ float g_xin[(size_t)MTOT * DD];
__device__ float g_xz [(size_t)MTOT * 4 * UU];
__device__ float g_hs [(size_t)MTOT * UU];

// 1 noop: keeps LSTM at the ncu capture slot
__global__ void noop_kernel(int* p) { if (p) *p = 0; }

// ---------------------------------------------------------------------------
// GEMM v2: C[M,N] = A[M,K] @ W[K,N] + bias[N]
// 128x128 block, BK=16, 256 threads, 8x8 per thread.
// Requires M%128==0, N%128==0, K%16==0 (holds for all three calls).
// ---------------------------------------------------------------------------
__global__ __launch_bounds__(256) void gemm_bias_kernel(
    const float* __restrict__ A, const float* __restrict__ W,
    const float* __restrict__ bias, float* __restrict__ C,
    int M, int N, int K)
{
    __shared__ float As[16][128];   // transposed A tile: As[k][m]
    __shared__ float Bs[16][128];   // Bs[k][n]

    const int tid = threadIdx.x;
    const int tx  = tid & 15;       // N-dir thread coord (8 cols)
    const int ty  = tid >> 4;       // M-dir thread coord (8 rows)
    const int m0  = blockIdx.y * 128;
    const int n0  = blockIdx.x * 128;

    const int arow = tid >> 1;              // 0..127
    const int acol = (tid & 1) * 8;         // 0 or 8
    const int brow = tid >> 4;              // 0..15
    const int bcol = (tid & 15) * 8;        // 0..120

    float acc[8][8];
    #pragma unroll
    for (int i = 0; i < 8; i++)
        #pragma unroll
        for (int j = 0; j < 8; j++) acc[i][j] = 0.f;

    for (int kt = 0; kt < K; kt += 16) {
        // A tile -> As transposed
        {
            const float* ap = &A[(size_t)(m0 + arow) * K + kt + acol];
            float4 a0 = *(const float4*)ap;
            float4 a1 = *(const float4*)(ap + 4);
            As[acol + 0][arow] = a0.x;
            As[acol + 1][arow] = a0.y;
            As[acol + 2][arow] = a0.z;
            As[acol + 3][arow] = a0.w;
            As[acol + 4][arow] = a1.x;
            As[acol + 5][arow] = a1.y;
            As[acol + 6][arow] = a1.z;
            As[acol + 7][arow] = a1.w;
        }
        // B tile
        {
            const float* bp = &W[(size_t)(kt + brow) * N + n0 + bcol];
            *(float4*)&Bs[brow][bcol]     = *(const float4*)bp;
            *(float4*)&Bs[brow][bcol + 4] = *(const float4*)(bp + 4);
        }
        __syncthreads();

        #pragma unroll
        for (int kk = 0; kk < 16; kk++) {
            float4 a0 = *(const float4*)&As[kk][ty * 8];
            float4 a1 = *(const float4*)&As[kk][ty * 8 + 4];
            float4 b0 = *(const float4*)&Bs[kk][tx * 8];
            float4 b1 = *(const float4*)&Bs[kk][tx * 8 + 4];
            float a[8] = {a0.x, a0.y, a0.z, a0.w, a1.x, a1.y, a1.z, a1.w};
            float b[8] = {b0.x, b0.y, b0.z, b0.w, b1.x, b1.y, b1.z, b1.w};
            #pragma unroll
            for (int i = 0; i < 8; i++)
                #pragma unroll
                for (int j = 0; j < 8; j++)
                    acc[i][j] += a[i] * b[j];
        }
        __syncthreads();
    }

    float4 bv0 = *(const float4*)&bias[n0 + tx * 8];
    float4 bv1 = *(const float4*)&bias[n0 + tx * 8 + 4];
    const float bb_[8] = {bv0.x, bv0.y, bv0.z, bv0.w, bv1.x, bv1.y, bv1.z, bv1.w};
    #pragma unroll
    for (int i = 0; i < 8; i++) {
        float* cp = &C[(size_t)(m0 + ty * 8 + i) * N + n0 + tx * 8];
        float4 o0, o1;
        o0.x = acc[i][0] + bb_[0];
        o0.y = acc[i][1] + bb_[1];
        o0.z = acc[i][2] + bb_[2];
        o0.w = acc[i][3] + bb_[3];
        o1.x = acc[i][4] + bb_[4];
        o1.y = acc[i][5] + bb_[5];
        o1.z = acc[i][6] + bb_[6];
        o1.w = acc[i][7] + bb_[7];
        *(float4*)cp       = o0;
        *(float4*)(cp + 4) = o1;
    }
}

// ---------------------------------------------------------------------------
// LSTM scan (exact revert to R5 best: v4, 256 threads). 2926us total baseline.
// ---------------------------------------------------------------------------
#define CLS 8
#define LSTM_THREADS 256

__device__ __forceinline__ float sigm_f(float x) {
    return 1.f / (1.f + __expf(-x));
}
__device__ __forceinline__ float tanh_f(float x) {
    return 2.f / (1.f + __expf(-2.f * x)) - 1.f;
}

#define FMA2(acc, a, b) \
    asm("fma.rn.f32x2 %0, %1, %2, %0;" : "+l"(acc) : "l"(a), "l"(b))

#define MBAR_INIT(addr, cnt) \
    asm volatile("mbarrier.init.shared.b64 [%0], %1;" :: "r"(addr), "r"(cnt) : "memory")

#define MBAR_EXPECT_TX(addr, tx) \
    asm volatile("mbarrier.arrive.expect_tx.shared.b64 _, [%0], %1;" :: "r"(addr), "r"(tx) : "memory")

#define MBAR_WAIT(addr, par) do {                                                  \
    asm volatile("{\n\t.reg .pred P;\n"                                            \
                 "W_%=:\n\t"                                                       \
                 "mbarrier.try_wait.parity.acquire.cluster.shared::cta.b64 "       \
                 "P, [%0], %1, 0x80;\n\t"                                          \
                 "@!P bra W_%=;\n\t}"                                              \
                 :: "r"(addr), "r"(par) : "memory");                               \
} while (0)

__global__ void __cluster_dims__(CLS, 1, 1) __launch_bounds__(LSTM_THREADS, 1)
lstm_kernel(const float* __restrict__ xz, const float* __restrict__ R,
            float* __restrict__ hs)
{
    __shared__ __align__(16) float h2[2 * 512];         // [buf][k=256][b=2]
    __shared__ __align__(16) float parts[2][16 * 128];  // [buf][w*2+b][c=128]
    __shared__ __align__(16) float hstage[64];          // [u=32][b=2]
    __shared__ __align__(8)  unsigned long long mbar[16]; // [buf][src=8]

    const int tid  = threadIdx.x;
    const int rank = blockIdx.x;
    const int b0   = blockIdx.y * 2;
    const int w    = tid >> 5;
    const int l    = tid & 31;

    // ---- R slice -> registers: thread (w,l) holds k=32w..32w+32, cols 4l..4l+3
    const int gate = l >> 3;
    const int cb   = (4 * l) & 31;
    const int gcol = gate * 256 + rank * 32 + cb;
    ulonglong2 Rreg[32];
    #pragma unroll
    for (int j = 0; j < 32; j++)
        Rreg[j] = *(const ulonglong2*)&R[(size_t)(w * 32 + j) * 1024 + gcol];

    for (int i = tid; i < 1024; i += LSTM_THREADS) h2[i] = 0.f;

    const unsigned mb0 = (unsigned)__cvta_generic_to_shared(&mbar[0]);
    if (tid == 0) {
        #pragma unroll
        for (int i = 0; i < 16; i++) {
            MBAR_INIT(mb0 + i * 8, 1);
            MBAR_EXPECT_TX(mb0 + i * 8, 256);
        }
        asm volatile("fence.mbarrier_init.release.cluster;" ::: "memory");
    }
    __syncthreads();
    asm volatile("barrier.cluster.arrive.aligned;" ::: "memory");
    asm volatile("barrier.cluster.wait.aligned;"   ::: "memory");

    const int gb = tid >> 5;            // gate-thread batch  (tid<64)
    const int gu = tid & 31;            // gate-thread unit
    float creg = 0.f;
    int ph0 = 0, ph1 = 0;

    const unsigned dst_l[2] = {
        (unsigned)__cvta_generic_to_shared(&h2[0 * 512 + rank * 64]),
        (unsigned)__cvta_generic_to_shared(&h2[1 * 512 + rank * 64])};
    const unsigned src_l =
        (unsigned)__cvta_generic_to_shared(&hstage[0]);

    for (int t = 0; t < TT; t++) {
        const int pb = t & 1;

        // xz prefetch (gate threads only), issued before any wait
        float xzv0 = 0.f, xzv1 = 0.f, xzv2 = 0.f, xzv3 = 0.f;
        if (tid < 64) {
            size_t base = ((size_t)(b0 + gb) * TT + t) * 1024 + rank * 32 + gu;
            xzv0 = xz[base];
            xzv1 = xz[base + 256];
            xzv2 = xz[base + 512];
            xzv3 = xz[base + 768];
        }

        // wait ONLY for our source slice (rank w -> units 32w..32w+32)
        if (t > 0) {
            const unsigned m = mb0 + (unsigned)((pb * 8 + w) * 8);
            if (pb) { MBAR_WAIT(m, ph1); ph1 ^= 1; }
            else    { MBAR_WAIT(m, ph0); ph0 ^= 1; }
            if (l == 0) MBAR_EXPECT_TX(m, 256);   // re-arm for t+2
        }

        // ---- MMA: z_partial over k in [32w,32w+32), cols 4l..4l+3, b=0,1
        unsigned long long a00 = 0ull, a01 = 0ull, a10 = 0ull, a11 = 0ull;
        const float2* hb = (const float2*)(h2 + pb * 512) + w * 32;
        #pragma unroll
        for (int j = 0; j < 32; j++) {
            float2 hh = hb[j];
            unsigned hx = __float_as_uint(hh.x);
            unsigned hy = __float_as_uint(hh.y);
            unsigned long long hp0, hp1;
            asm("mov.b64 %0, {%1, %1};" : "=l"(hp0) : "r"(hx));
            asm("mov.b64 %0, {%1, %1};" : "=l"(hp1) : "r"(hy));
            FMA2(a00, Rreg[j].x, hp0);
            FMA2(a01, Rreg[j].x, hp1);
            FMA2(a10, Rreg[j].y, hp0);
            FMA2(a11, Rreg[j].y, hp1);
        }
        {
            float* pbuf = parts[pb];
            unsigned p0, p1, p2, p3;
            asm("mov.b64 {%0, %1}, %2;" : "=r"(p0), "=r"(p1) : "l"(a00));
            asm("mov.b64 {%0, %1}, %2;" : "=r"(p2), "=r"(p3) : "l"(a10));
            *(float4*)&pbuf[(w * 2 + 0) * 128 + 4 * l] =
                make_float4(__uint_as_float(p0), __uint_as_float(p1),
                            __uint_as_float(p2), __uint_as_float(p3));
            asm("mov.b64 {%0, %1}, %2;" : "=r"(p0), "=r"(p1) : "l"(a01));
            asm("mov.b64 {%0, %1}, %2;" : "=r"(p2), "=r"(p3) : "l"(a11));
            *(float4*)&pbuf[(w * 2 + 1) * 128 + 4 * l] =
                make_float4(__uint_as_float(p0), __uint_as_float(p1),
                            __uint_as_float(p2), __uint_as_float(p3));
        }

        if (w >= 2) {
            asm volatile("bar.arrive 2, 256;" ::: "memory");
            continue;                      // run ahead into next step
        }
        asm volatile("bar.sync 2, 256;" ::: "memory");

        // ---- gate phase (warps 0,1 == 64 gate threads) ----
        {
            const float* pbuf = parts[pb];
            float z0 = xzv0, z1 = xzv1, z2 = xzv2, z3 = xzv3;
            #pragma unroll
            for (int ww = 0; ww < 8; ww++) {
                const float* p = &pbuf[(ww * 2 + gb) * 128];
                z0 += p[gu];
                z1 += p[32 + gu];
                z2 += p[64 + gu];
                z3 += p[96 + gu];
            }
            float ig = sigm_f(z0);
            float fg = sigm_f(z1);
            float gg = tanh_f(z2);
            float og = sigm_f(z3);
            creg = fg * creg + ig * gg;
            float h = og * tanh_f(creg);

            if (t < TT - 1) {
                hstage[gu * 2 + gb] = h;
                asm volatile("bar.sync 1, 64;" ::: "memory");
                if (tid < 8) {
                    asm volatile("fence.proxy.async.shared::cta;" ::: "memory");
                    const int nb = pb ^ 1;
                    const unsigned dl = dst_l[nb];
                    const unsigned ml = mb0 + (unsigned)((nb * 8 + rank) * 8);
                    unsigned rd, rm;
                    asm volatile("mapa.shared::cluster.u32 %0, %1, %2;"
                                 : "=r"(rd) : "r"(dl), "r"(tid));
                    asm volatile("mapa.shared::cluster.u32 %0, %1, %2;"
                                 : "=r"(rm) : "r"(ml), "r"(tid));
                    asm volatile(
                        "cp.async.bulk.shared::cluster.shared::cta"
                        ".mbarrier::complete_tx::bytes [%0], [%1], 256, [%2];"
                        :: "r"(rd), "r"(src_l), "r"(rm) : "memory");
                }
            }
            // global store off the critical path
            hs[((size_t)(b0 + gb) * TT + t) * UU + rank * 32 + gu] = h;
        }
    }

    asm volatile("barrier.cluster.arrive.aligned;" ::: "memory");
    asm volatile("barrier.cluster.wait.aligned;"   ::: "memory");
}

// ---------------------------------------------------------------------------
// launch
// ---------------------------------------------------------------------------
extern "C" void kernel_launch(void* const* d_in, const int* in_sizes, int n_in,
                              void* d_out, int out_size)
{
    const float* x      = (const float*)d_in[0];
    const float* w_in   = (const float*)d_in[1];
    const float* b_in   = (const float*)d_in[2];
    const float* kernel = (const float*)d_in[3];
    const float* rec_k  = (const float*)d_in[4];
    const float* bias   = (const float*)d_in[5];
    const float* w_out  = (const float*)d_in[6];
    const float* b_out  = (const float*)d_in[7];
    float* out = (float*)d_out;

    float *p_xin, *p_xz, *p_hs;
    cudaGetSymbolAddress((void**)&p_xin, g_xin);
    cudaGetSymbolAddress((void**)&p_xz,  g_xz);
    cudaGetSymbolAddress((void**)&p_hs,  g_hs);

    // 1 noop: LSTM stays at the ncu capture index
    noop_kernel<<<1, 32>>>(nullptr);

    // 1) xin = x @ w_in + b_in          [32768,512]x[512,256]
    gemm_bias_kernel<<<dim3(DD / 128, MTOT / 128), 256>>>(
        x, w_in, b_in, p_xin, MTOT, DD, CC);

    // 2) xz = xin @ kernel + bias       [32768,256]x[256,1024]
    gemm_bias_kernel<<<dim3((4 * UU) / 128, MTOT / 128), 256>>>(
        p_xin, kernel, bias, p_xz, MTOT, 4 * UU, DD);

    // 3) LSTM scan over T=1024
    lstm_kernel<<<dim3(CLS, BB / 2), LSTM_THREADS>>>(p_xz, rec_k, p_hs);

    // 4) out = hs @ w_out + b_out       [32768,256]x[256,256]
    gemm_bias_kernel<<<dim3(OO / 128, MTOT / 128), 256>>>(
        p_hs, w_out, b_out, out, MTOT, OO, UU);
}

// round 9
// speedup vs baseline: 1.7402x; 1.1144x over previous
#include <cuda_runtime.h>
#include <cstdint>

// ---------------------------------------------------------------------------
// Problem constants
// ---------------------------------------------------------------------------
#define BB    32
#define TT    1024
#define CC    512
#define DD    256
#define UU    256
#define OO    256
#define MTOT  (BB*TT)          // 32768

__device__ float g_xin[(size_t)MTOT * DD];
__device__ float g_xz [(size_t)MTOT * 4 * UU];
__device__ float g_hs [(size_t)MTOT * UU];

// 1 noop: keeps LSTM at the ncu capture slot
__global__ void noop_kernel(int* p) { if (p) *p = 0; }

// ---------------------------------------------------------------------------
// Tiled fp32 GEMM (R2 version, proven): C[M,N] = A[M,K] @ W[K,N] + bias[N]
// ---------------------------------------------------------------------------
__global__ __launch_bounds__(256) void gemm_bias_kernel(
    const float* __restrict__ A, const float* __restrict__ W,
    const float* __restrict__ bias, float* __restrict__ C,
    int M, int N, int K)
{
    __shared__ float As[16][128];
    __shared__ float Bs[16][64];

    const int tid = threadIdx.x;
    const int tx  = tid & 15;
    const int ty  = tid >> 4;
    const int m0  = blockIdx.y * 128;
    const int n0  = blockIdx.x * 64;

    const int arow = tid >> 2;
    const int akc  = (tid & 3) * 4;
    const int brow = tid >> 4;
    const int bnc  = (tid & 15) * 4;

    float acc[8][4];
    #pragma unroll
    for (int i = 0; i < 8; i++)
        #pragma unroll
        for (int j = 0; j < 4; j++) acc[i][j] = 0.f;

    for (int kt = 0; kt < K; kt += 16) {
        #pragma unroll
        for (int h = 0; h < 2; h++) {
            int r = arow + h * 64;
            float4 a = *(const float4*)&A[(size_t)(m0 + r) * K + kt + akc];
            As[akc + 0][r] = a.x;
            As[akc + 1][r] = a.y;
            As[akc + 2][r] = a.z;
            As[akc + 3][r] = a.w;
        }
        {
            float4 b = *(const float4*)&W[(size_t)(kt + brow) * N + n0 + bnc];
            *(float4*)&Bs[brow][bnc] = b;
        }
        __syncthreads();

        #pragma unroll
        for (int kk = 0; kk < 16; kk++) {
            float4 b4 = *(const float4*)&Bs[kk][tx * 4];
            float4 a0 = *(const float4*)&As[kk][ty * 8];
            float4 a1 = *(const float4*)&As[kk][ty * 8 + 4];
            float a[8] = {a0.x, a0.y, a0.z, a0.w, a1.x, a1.y, a1.z, a1.w};
            #pragma unroll
            for (int i = 0; i < 8; i++) {
                acc[i][0] += a[i] * b4.x;
                acc[i][1] += a[i] * b4.y;
                acc[i][2] += a[i] * b4.z;
                acc[i][3] += a[i] * b4.w;
            }
        }
        __syncthreads();
    }

    float4 bv = *(const float4*)&bias[n0 + tx * 4];
    #pragma unroll
    for (int i = 0; i < 8; i++) {
        float4 o;
        o.x = acc[i][0] + bv.x;
        o.y = acc[i][1] + bv.y;
        o.z = acc[i][2] + bv.z;
        o.w = acc[i][3] + bv.w;
        *(float4*)&C[(size_t)(m0 + ty * 8 + i) * N + n0 + tx * 4] = o;
    }
}

// ---------------------------------------------------------------------------
// LSTM scan v7 = v4 (proven best) + xz prefetched ONE FULL STEP ahead
// (register double-buffer) + hoisted mapa.
// ---------------------------------------------------------------------------
#define CLS 8
#define LSTM_THREADS 256

__device__ __forceinline__ float sigm_f(float x) {
    return 1.f / (1.f + __expf(-x));
}
__device__ __forceinline__ float tanh_f(float x) {
    return 2.f / (1.f + __expf(-2.f * x)) - 1.f;
}

#define FMA2(acc, a, b) \
    asm("fma.rn.f32x2 %0, %1, %2, %0;" : "+l"(acc) : "l"(a), "l"(b))

#define MBAR_INIT(addr, cnt) \
    asm volatile("mbarrier.init.shared.b64 [%0], %1;" :: "r"(addr), "r"(cnt) : "memory")

#define MBAR_EXPECT_TX(addr, tx) \
    asm volatile("mbarrier.arrive.expect_tx.shared.b64 _, [%0], %1;" :: "r"(addr), "r"(tx) : "memory")

#define MBAR_WAIT(addr, par) do {                                                  \
    asm volatile("{\n\t.reg .pred P;\n"                                            \
                 "W_%=:\n\t"                                                       \
                 "mbarrier.try_wait.parity.acquire.cluster.shared::cta.b64 "       \
                 "P, [%0], %1, 0x80;\n\t"                                          \
                 "@!P bra W_%=;\n\t}"                                              \
                 :: "r"(addr), "r"(par) : "memory");                               \
} while (0)

__global__ void __cluster_dims__(CLS, 1, 1) __launch_bounds__(LSTM_THREADS, 1)
lstm_kernel(const float* __restrict__ xz, const float* __restrict__ R,
            float* __restrict__ hs)
{
    __shared__ __align__(16) float h2[2 * 512];         // [buf][k=256][b=2]
    __shared__ __align__(16) float parts[2][16 * 128];  // [buf][w*2+b][c=128]
    __shared__ __align__(16) float hstage[64];          // [u=32][b=2]
    __shared__ __align__(8)  unsigned long long mbar[16]; // [buf][src=8]

    const int tid  = threadIdx.x;
    const int rank = blockIdx.x;
    const int b0   = blockIdx.y * 2;
    const int w    = tid >> 5;
    const int l    = tid & 31;

    // ---- R slice -> registers: thread (w,l) holds k=32w..32w+32, cols 4l..4l+3
    const int gate = l >> 3;
    const int cb   = (4 * l) & 31;
    const int gcol = gate * 256 + rank * 32 + cb;
    ulonglong2 Rreg[32];
    #pragma unroll
    for (int j = 0; j < 32; j++)
        Rreg[j] = *(const ulonglong2*)&R[(size_t)(w * 32 + j) * 1024 + gcol];

    for (int i = tid; i < 1024; i += LSTM_THREADS) h2[i] = 0.f;

    const unsigned mb0 = (unsigned)__cvta_generic_to_shared(&mbar[0]);
    if (tid == 0) {
        #pragma unroll
        for (int i = 0; i < 16; i++) {
            MBAR_INIT(mb0 + i * 8, 1);
            MBAR_EXPECT_TX(mb0 + i * 8, 256);
        }
        asm volatile("fence.mbarrier_init.release.cluster;" ::: "memory");
    }
    __syncthreads();
    asm volatile("barrier.cluster.arrive.aligned;" ::: "memory");
    asm volatile("barrier.cluster.wait.aligned;"   ::: "memory");

    const int gb = tid >> 5;            // gate-thread batch  (tid<64)
    const int gu = tid & 31;            // gate-thread unit
    float creg = 0.f;
    int ph0 = 0, ph1 = 0;

    const unsigned dst_l[2] = {
        (unsigned)__cvta_generic_to_shared(&h2[0 * 512 + rank * 64]),
        (unsigned)__cvta_generic_to_shared(&h2[1 * 512 + rank * 64])};
    const unsigned src_l =
        (unsigned)__cvta_generic_to_shared(&hstage[0]);

    // hoisted remote addresses for the bulk push (threads 0..7)
    unsigned rdl = 0, rml = 0;
    if (tid < 8) {
        asm volatile("mapa.shared::cluster.u32 %0, %1, %2;"
                     : "=r"(rdl) : "r"(dst_l[0]), "r"(tid));
        asm volatile("mapa.shared::cluster.u32 %0, %1, %2;"
                     : "=r"(rml) : "r"(mb0 + (unsigned)(rank * 8)), "r"(tid));
    }

    // ---- xz prefetch pipeline: load t=0 now; inside step t we load t+1 ----
    const float* xzp = (tid < 64)
        ? &xz[((size_t)(b0 + gb) * TT) * 1024 + rank * 32 + gu] : xz;
    float xzv0 = 0.f, xzv1 = 0.f, xzv2 = 0.f, xzv3 = 0.f;
    if (tid < 64) {
        xzv0 = xzp[0];
        xzv1 = xzp[256];
        xzv2 = xzp[512];
        xzv3 = xzp[768];
    }

    for (int t = 0; t < TT; t++) {
        const int pb = t & 1;

        // prefetch xz for t+1 (consumed in NEXT step's gate phase:
        // distance = one full step, covers DRAM latency)
        float nx0 = 0.f, nx1 = 0.f, nx2 = 0.f, nx3 = 0.f;
        if (tid < 64 && t + 1 < TT) {
            const float* p = xzp + (size_t)(t + 1) * 1024;
            nx0 = p[0];
            nx1 = p[256];
            nx2 = p[512];
            nx3 = p[768];
        }

        // wait ONLY for our source slice (rank w -> units 32w..32w+32)
        if (t > 0) {
            const unsigned m = mb0 + (unsigned)((pb * 8 + w) * 8);
            if (pb) { MBAR_WAIT(m, ph1); ph1 ^= 1; }
            else    { MBAR_WAIT(m, ph0); ph0 ^= 1; }
            if (l == 0) MBAR_EXPECT_TX(m, 256);   // re-arm for t+2
        }

        // ---- MMA: z_partial over k in [32w,32w+32), cols 4l..4l+3, b=0,1
        unsigned long long a00 = 0ull, a01 = 0ull, a10 = 0ull, a11 = 0ull;
        const float2* hb = (const float2*)(h2 + pb * 512) + w * 32;
        #pragma unroll
        for (int j = 0; j < 32; j++) {
            float2 hh = hb[j];
            unsigned hx = __float_as_uint(hh.x);
            unsigned hy = __float_as_uint(hh.y);
            unsigned long long hp0, hp1;
            asm("mov.b64 %0, {%1, %1};" : "=l"(hp0) : "r"(hx));
            asm("mov.b64 %0, {%1, %1};" : "=l"(hp1) : "r"(hy));
            FMA2(a00, Rreg[j].x, hp0);
            FMA2(a01, Rreg[j].x, hp1);
            FMA2(a10, Rreg[j].y, hp0);
            FMA2(a11, Rreg[j].y, hp1);
        }
        {
            float* pbuf = parts[pb];
            unsigned p0, p1, p2, p3;
            asm("mov.b64 {%0, %1}, %2;" : "=r"(p0), "=r"(p1) : "l"(a00));
            asm("mov.b64 {%0, %1}, %2;" : "=r"(p2), "=r"(p3) : "l"(a10));
            *(float4*)&pbuf[(w * 2 + 0) * 128 + 4 * l] =
                make_float4(__uint_as_float(p0), __uint_as_float(p1),
                            __uint_as_float(p2), __uint_as_float(p3));
            asm("mov.b64 {%0, %1}, %2;" : "=r"(p0), "=r"(p1) : "l"(a01));
            asm("mov.b64 {%0, %1}, %2;" : "=r"(p2), "=r"(p3) : "l"(a11));
            *(float4*)&pbuf[(w * 2 + 1) * 128 + 4 * l] =
                make_float4(__uint_as_float(p0), __uint_as_float(p1),
                            __uint_as_float(p2), __uint_as_float(p3));
        }

        if (w >= 2) {
            asm volatile("bar.arrive 2, 256;" ::: "memory");
            // carry pipeline regs (no-op for these threads)
            xzv0 = nx0; xzv1 = nx1; xzv2 = nx2; xzv3 = nx3;
            continue;                      // run ahead into next step
        }
        asm volatile("bar.sync 2, 256;" ::: "memory");

        // ---- gate phase (warps 0,1 == 64 gate threads) ----
        {
            const float* pbuf = parts[pb];
            float z0 = xzv0, z1 = xzv1, z2 = xzv2, z3 = xzv3;
            #pragma unroll
            for (int ww = 0; ww < 8; ww++) {
                const float* p = &pbuf[(ww * 2 + gb) * 128];
                z0 += p[gu];
                z1 += p[32 + gu];
                z2 += p[64 + gu];
                z3 += p[96 + gu];
            }
            float ig = sigm_f(z0);
            float fg = sigm_f(z1);
            float gg = tanh_f(z2);
            float og = sigm_f(z3);
            creg = fg * creg + ig * gg;
            float h = og * tanh_f(creg);

            if (t < TT - 1) {
                hstage[gu * 2 + gb] = h;
                asm volatile("bar.sync 1, 64;" ::: "memory");
                if (tid < 8) {
                    asm volatile("fence.proxy.async.shared::cta;" ::: "memory");
                    const int nb = pb ^ 1;
                    const unsigned rd = rdl + (unsigned)(nb * 2048);
                    const unsigned rm = rml + (unsigned)(nb * 64);
                    asm volatile(
                        "cp.async.bulk.shared::cluster.shared::cta"
                        ".mbarrier::complete_tx::bytes [%0], [%1], 256, [%2];"
                        :: "r"(rd), "r"(src_l), "r"(rm) : "memory");
                }
            }
            // global store off the critical path
            hs[((size_t)(b0 + gb) * TT + t) * UU + rank * 32 + gu] = h;
        }
        xzv0 = nx0; xzv1 = nx1; xzv2 = nx2; xzv3 = nx3;
    }

    asm volatile("barrier.cluster.arrive.aligned;" ::: "memory");
    asm volatile("barrier.cluster.wait.aligned;"   ::: "memory");
}

// ---------------------------------------------------------------------------
// launch
// ---------------------------------------------------------------------------
extern "C" void kernel_launch(void* const* d_in, const int* in_sizes, int n_in,
                              void* d_out, int out_size)
{
    const float* x      = (const float*)d_in[0];
    const float* w_in   = (const float*)d_in[1];
    const float* b_in   = (const float*)d_in[2];
    const float* kernel = (const float*)d_in[3];
    const float* rec_k  = (const float*)d_in[4];
    const float* bias   = (const float*)d_in[5];
    const float* w_out  = (const float*)d_in[6];
    const float* b_out  = (const float*)d_in[7];
    float* out = (float*)d_out;

    float *p_xin, *p_xz, *p_hs;
    cudaGetSymbolAddress((void**)&p_xin, g_xin);
    cudaGetSymbolAddress((void**)&p_xz,  g_xz);
    cudaGetSymbolAddress((void**)&p_hs,  g_hs);

    // 1 noop: LSTM stays at the ncu capture index
    noop_kernel<<<1, 32>>>(nullptr);

    // 1) xin = x @ w_in + b_in          [32768,512]x[512,256]
    gemm_bias_kernel<<<dim3(DD / 64, MTOT / 128), 256>>>(
        x, w_in, b_in, p_xin, MTOT, DD, CC);

    // 2) xz = xin @ kernel + bias       [32768,256]x[256,1024]
    gemm_bias_kernel<<<dim3((4 * UU) / 64, MTOT / 128), 256>>>(
        p_xin, kernel, bias, p_xz, MTOT, 4 * UU, DD);

    // 3) LSTM scan over T=1024
    lstm_kernel<<<dim3(CLS, BB / 2), LSTM_THREADS>>>(p_xz, rec_k, p_hs);

    // 4) out = hs @ w_out + b_out       [32768,256]x[256,256]
    gemm_bias_kernel<<<dim3(OO / 64, MTOT / 128), 256>>>(
        p_hs, w_out, b_out, out, MTOT, OO, UU);
}